// round 1
// baseline (speedup 1.0000x reference)
#include <cuda_runtime.h>
#include <cstdint>

#define T_DIM 512
#define N_DIM 32
#define C_DIM 1296
#define D_DIM 512
#define S_DIM 30
#define L_DIM 61
#define NEGINF -1e9f
#define NORM_SCALE 32.0f

// ---------------- scratch (static device globals; no allocation) -------------
__device__ float g_logits[(size_t)T_DIM * N_DIM * C_DIM];   // 84.9 MB
__device__ float g_row_inv[T_DIM * N_DIM];
__device__ float g_col_inv[C_DIM];
__device__ float g_lp[(size_t)N_DIM * T_DIM * L_DIM];       // (n, t, l) layout
__device__ float g_nll[N_DIM];

// ---------------- K1: column inverse norms of classifier weight -------------
__global__ void col_norm_kernel(const float* __restrict__ w) {
    int c = blockIdx.x * blockDim.x + threadIdx.x;
    if (c >= C_DIM) return;
    float s = 0.f;
    #pragma unroll 4
    for (int d = 0; d < D_DIM; d++) {
        float v = w[d * C_DIM + c];
        s += v * v;
    }
    g_col_inv[c] = rsqrtf(s);
}

// ---------------- K2: row inverse norms of feats (one warp per row) ---------
__global__ void row_norm_kernel(const float* __restrict__ f) {
    int warp = (blockIdx.x * blockDim.x + threadIdx.x) >> 5;
    int lane = threadIdx.x & 31;
    if (warp >= T_DIM * N_DIM) return;
    const float* row = f + (size_t)warp * D_DIM;
    float s = 0.f;
    #pragma unroll
    for (int j = 0; j < D_DIM / 32; j++) {
        float v = row[lane + j * 32];
        s += v * v;
    }
    #pragma unroll
    for (int off = 16; off > 0; off >>= 1)
        s += __shfl_down_sync(0xffffffffu, s, off);
    if (lane == 0) g_row_inv[warp] = rsqrtf(s);
}

// ---------------- K3: SGEMM with packed fp32x2 FMA (FFMA2) ------------------
// logits[m, c] = 32 * row_inv[m] * col_inv[c] * sum_k f[m,k] * w[k,c]
// block tile 128x128, BK=8, 256 threads, 8x8 per thread (as 8x4 f32x2 pairs)
#define BM 128
#define BN 128
#define BK 8

__global__ __launch_bounds__(256, 2) void gemm_kernel(
    const float* __restrict__ A, const float* __restrict__ B) {
    __shared__ unsigned long long As2[BK][BM];  // (a, a) duplicated pairs
    __shared__ float Bs[BK][BN];

    const int tid = threadIdx.x;
    const int m0 = blockIdx.y * BM;
    const int n0 = blockIdx.x * BN;
    const int tx = tid & 15;
    const int ty = tid >> 4;

    unsigned long long acc[8][4];
    #pragma unroll
    for (int i = 0; i < 8; i++)
        #pragma unroll
        for (int j = 0; j < 4; j++) acc[i][j] = 0ULL;

    const int aRow = tid >> 1;
    const int aCol = (tid & 1) * 4;
    const int bRow = tid >> 5;
    const int bCol = (tid & 31) * 4;

    const float* Aptr = A + (size_t)(m0 + aRow) * D_DIM + aCol;

    for (int k0 = 0; k0 < D_DIM; k0 += BK) {
        // stage A (duplicated f32x2 packs, transposed)
        float4 av = *(const float4*)(Aptr + k0);
        unsigned long long p;
        asm("mov.b64 %0,{%1,%1};" : "=l"(p) : "f"(av.x)); As2[aCol + 0][aRow] = p;
        asm("mov.b64 %0,{%1,%1};" : "=l"(p) : "f"(av.y)); As2[aCol + 1][aRow] = p;
        asm("mov.b64 %0,{%1,%1};" : "=l"(p) : "f"(av.z)); As2[aCol + 2][aRow] = p;
        asm("mov.b64 %0,{%1,%1};" : "=l"(p) : "f"(av.w)); As2[aCol + 3][aRow] = p;
        // stage B
        float4 bv;
        int col = n0 + bCol;
        if (col < C_DIM) bv = *(const float4*)(B + (size_t)(k0 + bRow) * C_DIM + col);
        else bv = make_float4(0.f, 0.f, 0.f, 0.f);
        *(float4*)&Bs[bRow][bCol] = bv;
        __syncthreads();

        #pragma unroll
        for (int k = 0; k < BK; k++) {
            ulonglong2 aq0 = *(const ulonglong2*)&As2[k][ty * 8 + 0];
            ulonglong2 aq1 = *(const ulonglong2*)&As2[k][ty * 8 + 2];
            ulonglong2 aq2 = *(const ulonglong2*)&As2[k][ty * 8 + 4];
            ulonglong2 aq3 = *(const ulonglong2*)&As2[k][ty * 8 + 6];
            unsigned long long a2[8] = {aq0.x, aq0.y, aq1.x, aq1.y,
                                        aq2.x, aq2.y, aq3.x, aq3.y};
            ulonglong2 bq0 = *(const ulonglong2*)&Bs[k][tx * 8];
            ulonglong2 bq1 = *(const ulonglong2*)&Bs[k][tx * 8 + 4];
            unsigned long long b2[4] = {bq0.x, bq0.y, bq1.x, bq1.y};
            #pragma unroll
            for (int i = 0; i < 8; i++) {
                #pragma unroll
                for (int j = 0; j < 4; j++) {
                    asm("fma.rn.f32x2 %0, %1, %2, %0;"
                        : "+l"(acc[i][j]) : "l"(a2[i]), "l"(b2[j]));
                }
            }
        }
        __syncthreads();
    }

    // epilogue: scale by 32 * row_inv * col_inv, bounds-check columns
    #pragma unroll
    for (int i = 0; i < 8; i++) {
        int m = m0 + ty * 8 + i;
        float rv = NORM_SCALE * g_row_inv[m];
        float* outrow = g_logits + (size_t)m * C_DIM;
        #pragma unroll
        for (int j = 0; j < 4; j++) {
            float lo, hi;
            asm("mov.b64 {%0,%1}, %2;" : "=f"(lo), "=f"(hi) : "l"(acc[i][j]));
            int c = n0 + tx * 8 + 2 * j;
            if (c < C_DIM)     outrow[c]     = rv * g_col_inv[c]     * lo;
            if (c + 1 < C_DIM) outrow[c + 1] = rv * g_col_inv[c + 1] * hi;
        }
    }
}

// ---------------- K4: per-row LSE + gather ext-label log-probs --------------
// one block per row (t, n); writes g_lp[(n*T + t)*61 + l]
__global__ __launch_bounds__(128) void lse_gather_kernel(const int* __restrict__ labeling) {
    const int row = blockIdx.x;               // row = t*N + n
    const int tid = threadIdx.x;
    const float* lg = g_logits + (size_t)row * C_DIM;

    float m = __int_as_float(0xff800000);     // -inf
    float s = 0.f;
    for (int c = tid; c < C_DIM; c += 128) {
        float x = lg[c];
        float mm = fmaxf(m, x);
        s = s * expf(m - mm) + expf(x - mm);
        m = mm;
    }
    __shared__ float sm[128], ss[128];
    sm[tid] = m; ss[tid] = s;
    __syncthreads();
    for (int off = 64; off > 0; off >>= 1) {
        if (tid < off) {
            float m2 = sm[tid + off], s2 = ss[tid + off];
            float mm = fmaxf(sm[tid], m2);
            ss[tid] = ss[tid] * expf(sm[tid] - mm) + s2 * expf(m2 - mm);
            sm[tid] = mm;
        }
        __syncthreads();
    }
    float lse = sm[0] + logf(ss[0]);

    if (tid < L_DIM) {
        int t = row / N_DIM;
        int n = row % N_DIM;
        int ext = (tid & 1) ? labeling[n * S_DIM + (tid >> 1)] : 0;
        g_lp[((size_t)n * T_DIM + t) * L_DIM + tid] = lg[ext] - lse;
    }
}

// ---------------- K5: CTC alpha recursion (one block per sequence) ----------
__global__ __launch_bounds__(64) void ctc_kernel(
    const int* __restrict__ labeling,
    const int* __restrict__ in_lens,
    const int* __restrict__ lab_lens) {
    const int n = blockIdx.x;
    const int l = threadIdx.x;
    const bool active = l < L_DIM;

    __shared__ float alpha[L_DIM];
    __shared__ int ext[L_DIM];
    if (active) ext[l] = (l & 1) ? labeling[n * S_DIM + (l >> 1)] : 0;
    __syncthreads();
    const bool skip = active && (l >= 2) && (l & 1) && (ext[l] != ext[l - 2]);

    const float* lp_n = g_lp + (size_t)n * T_DIM * L_DIM;
    const int Tlen = in_lens[n];

    if (active) alpha[l] = (l < 2) ? lp_n[l] : NEGINF;
    __syncthreads();

    float lp_cur = active ? lp_n[L_DIM + l] : 0.f;   // t = 1
    for (int t = 1; t < Tlen; t++) {
        float lp_next = (active && (t + 1 < Tlen)) ? lp_n[(t + 1) * L_DIM + l] : 0.f;
        float nv = 0.f;
        if (active) {
            float a1 = alpha[l];
            float a2 = (l >= 1) ? alpha[l - 1] : NEGINF;
            float a3 = skip ? alpha[l - 2] : NEGINF;
            float mx = fmaxf(a1, fmaxf(a2, a3));
            float sum = expf(a1 - mx) + expf(a2 - mx) + expf(a3 - mx);
            nv = mx + logf(sum) + lp_cur;
        }
        __syncthreads();
        if (active) alpha[l] = nv;
        __syncthreads();
        lp_cur = lp_next;
    }

    if (l == 0) {
        int Ln = 2 * lab_lens[n] + 1;
        float x = alpha[Ln - 1], y = alpha[Ln - 2];
        float mx = fmaxf(x, y);
        g_nll[n] = -(mx + logf(expf(x - mx) + expf(y - mx)));
    }
}

// ---------------- K6: final sum (fixed order -> deterministic) --------------
__global__ void sum_kernel(float* __restrict__ out) {
    float s = 0.f;
    #pragma unroll
    for (int n = 0; n < N_DIM; n++) s += g_nll[n];
    out[0] = s;
}

// ---------------- launch -----------------------------------------------------
extern "C" void kernel_launch(void* const* d_in, const int* in_sizes, int n_in,
                              void* d_out, int out_size) {
    const float* feats   = (const float*)d_in[0];   // (T*N, D)
    const float* weight  = (const float*)d_in[1];   // (D, C)
    const int*   labeling = (const int*)d_in[2];    // (N, S)
    const int*   logit_lgts = (const int*)d_in[3];  // (N,)
    const int*   labeling_lgts = (const int*)d_in[4]; // (N,)
    float* out = (float*)d_out;

    col_norm_kernel<<<(C_DIM + 255) / 256, 256>>>(weight);
    row_norm_kernel<<<(T_DIM * N_DIM) / 8, 256>>>(feats);

    dim3 grid((C_DIM + BN - 1) / BN, (T_DIM * N_DIM) / BM);
    gemm_kernel<<<grid, 256>>>(feats, weight);

    lse_gather_kernel<<<T_DIM * N_DIM, 128>>>(labeling);
    ctc_kernel<<<N_DIM, 64>>>(labeling, logit_lgts, labeling_lgts);
    sum_kernel<<<1, 1>>>(out);
}

// round 2
// speedup vs baseline: 1.0011x; 1.0011x over previous
#include <cuda_runtime.h>
#include <cstdint>

#define T_DIM 512
#define N_DIM 32
#define C_DIM 1296
#define D_DIM 512
#define S_DIM 30
#define L_DIM 61
#define NEGINF -1e9f
#define NORM_SCALE 32.0f

// ---------------- scratch (static device globals; no allocation) -------------
__device__ float g_logits[(size_t)T_DIM * N_DIM * C_DIM];   // 84.9 MB
__device__ float g_row_inv[T_DIM * N_DIM];
__device__ float g_col_inv[C_DIM];
__device__ float g_lp[(size_t)N_DIM * T_DIM * L_DIM];       // (n, t, l) layout
__device__ float g_nll[N_DIM];

// ---------------- K1: column inverse norms of classifier weight -------------
__global__ void col_norm_kernel(const float* __restrict__ w) {
    int c = blockIdx.x * blockDim.x + threadIdx.x;
    if (c >= C_DIM) return;
    float s = 0.f;
    #pragma unroll 4
    for (int d = 0; d < D_DIM; d++) {
        float v = w[d * C_DIM + c];
        s += v * v;
    }
    g_col_inv[c] = rsqrtf(s);
}

// ---------------- K2: row inverse norms of feats (one warp per row) ---------
__global__ void row_norm_kernel(const float* __restrict__ f) {
    int warp = (blockIdx.x * blockDim.x + threadIdx.x) >> 5;
    int lane = threadIdx.x & 31;
    if (warp >= T_DIM * N_DIM) return;
    const float* row = f + (size_t)warp * D_DIM;
    float s = 0.f;
    #pragma unroll
    for (int j = 0; j < D_DIM / 32; j++) {
        float v = row[lane + j * 32];
        s += v * v;
    }
    #pragma unroll
    for (int off = 16; off > 0; off >>= 1)
        s += __shfl_down_sync(0xffffffffu, s, off);
    if (lane == 0) g_row_inv[warp] = rsqrtf(s);
}

// ---------------- K3: SGEMM with packed fp32x2 FMA (FFMA2) ------------------
// logits[m, c] = 32 * row_inv[m] * col_inv[c] * sum_k f[m,k] * w[k,c]
// block tile 128x128, BK=8, 256 threads, 8x8 per thread (as 8x4 f32x2 pairs)
#define BM 128
#define BN 128
#define BK 8

__global__ __launch_bounds__(256, 2) void gemm_kernel(
    const float* __restrict__ A, const float* __restrict__ B) {
    __shared__ unsigned long long As2[BK][BM];  // (a, a) duplicated pairs
    __shared__ float Bs[BK][BN];

    const int tid = threadIdx.x;
    const int m0 = blockIdx.y * BM;
    const int n0 = blockIdx.x * BN;
    const int tx = tid & 15;
    const int ty = tid >> 4;

    unsigned long long acc[8][4];
    #pragma unroll
    for (int i = 0; i < 8; i++)
        #pragma unroll
        for (int j = 0; j < 4; j++) acc[i][j] = 0ULL;

    const int aRow = tid >> 1;
    const int aCol = (tid & 1) * 4;
    const int bRow = tid >> 5;
    const int bCol = (tid & 31) * 4;

    const float* Aptr = A + (size_t)(m0 + aRow) * D_DIM + aCol;

    for (int k0 = 0; k0 < D_DIM; k0 += BK) {
        // stage A (duplicated f32x2 packs, transposed)
        float4 av = *(const float4*)(Aptr + k0);
        unsigned long long p;
        asm("mov.b64 %0,{%1,%1};" : "=l"(p) : "f"(av.x)); As2[aCol + 0][aRow] = p;
        asm("mov.b64 %0,{%1,%1};" : "=l"(p) : "f"(av.y)); As2[aCol + 1][aRow] = p;
        asm("mov.b64 %0,{%1,%1};" : "=l"(p) : "f"(av.z)); As2[aCol + 2][aRow] = p;
        asm("mov.b64 %0,{%1,%1};" : "=l"(p) : "f"(av.w)); As2[aCol + 3][aRow] = p;
        // stage B
        float4 bv;
        int col = n0 + bCol;
        if (col < C_DIM) bv = *(const float4*)(B + (size_t)(k0 + bRow) * C_DIM + col);
        else bv = make_float4(0.f, 0.f, 0.f, 0.f);
        *(float4*)&Bs[bRow][bCol] = bv;
        __syncthreads();

        #pragma unroll
        for (int k = 0; k < BK; k++) {
            ulonglong2 aq0 = *(const ulonglong2*)&As2[k][ty * 8 + 0];
            ulonglong2 aq1 = *(const ulonglong2*)&As2[k][ty * 8 + 2];
            ulonglong2 aq2 = *(const ulonglong2*)&As2[k][ty * 8 + 4];
            ulonglong2 aq3 = *(const ulonglong2*)&As2[k][ty * 8 + 6];
            unsigned long long a2[8] = {aq0.x, aq0.y, aq1.x, aq1.y,
                                        aq2.x, aq2.y, aq3.x, aq3.y};
            ulonglong2 bq0 = *(const ulonglong2*)&Bs[k][tx * 8];
            ulonglong2 bq1 = *(const ulonglong2*)&Bs[k][tx * 8 + 4];
            unsigned long long b2[4] = {bq0.x, bq0.y, bq1.x, bq1.y};
            #pragma unroll
            for (int i = 0; i < 8; i++) {
                #pragma unroll
                for (int j = 0; j < 4; j++) {
                    asm("fma.rn.f32x2 %0, %1, %2, %0;"
                        : "+l"(acc[i][j]) : "l"(a2[i]), "l"(b2[j]));
                }
            }
        }
        __syncthreads();
    }

    // epilogue: scale by 32 * row_inv * col_inv, bounds-check columns
    #pragma unroll
    for (int i = 0; i < 8; i++) {
        int m = m0 + ty * 8 + i;
        float rv = NORM_SCALE * g_row_inv[m];
        float* outrow = g_logits + (size_t)m * C_DIM;
        #pragma unroll
        for (int j = 0; j < 4; j++) {
            float lo, hi;
            asm("mov.b64 {%0,%1}, %2;" : "=f"(lo), "=f"(hi) : "l"(acc[i][j]));
            int c = n0 + tx * 8 + 2 * j;
            if (c < C_DIM)     outrow[c]     = rv * g_col_inv[c]     * lo;
            if (c + 1 < C_DIM) outrow[c + 1] = rv * g_col_inv[c + 1] * hi;
        }
    }
}

// ---------------- K4: per-row LSE + gather ext-label log-probs --------------
// one block per row (t, n); writes g_lp[(n*T + t)*61 + l]
__global__ __launch_bounds__(128) void lse_gather_kernel(const int* __restrict__ labeling) {
    const int row = blockIdx.x;               // row = t*N + n
    const int tid = threadIdx.x;
    const float* lg = g_logits + (size_t)row * C_DIM;

    float m = __int_as_float(0xff800000);     // -inf
    float s = 0.f;
    for (int c = tid; c < C_DIM; c += 128) {
        float x = lg[c];
        float mm = fmaxf(m, x);
        s = s * expf(m - mm) + expf(x - mm);
        m = mm;
    }
    __shared__ float sm[128], ss[128];
    sm[tid] = m; ss[tid] = s;
    __syncthreads();
    for (int off = 64; off > 0; off >>= 1) {
        if (tid < off) {
            float m2 = sm[tid + off], s2 = ss[tid + off];
            float mm = fmaxf(sm[tid], m2);
            ss[tid] = ss[tid] * expf(sm[tid] - mm) + s2 * expf(m2 - mm);
            sm[tid] = mm;
        }
        __syncthreads();
    }
    float lse = sm[0] + logf(ss[0]);

    if (tid < L_DIM) {
        int t = row / N_DIM;
        int n = row % N_DIM;
        int ext = (tid & 1) ? labeling[n * S_DIM + (tid >> 1)] : 0;
        g_lp[((size_t)n * T_DIM + t) * L_DIM + tid] = lg[ext] - lse;
    }
}

// ---------------- K5: CTC alpha recursion (one block per sequence) ----------
__global__ __launch_bounds__(64) void ctc_kernel(
    const int* __restrict__ labeling,
    const int* __restrict__ in_lens,
    const int* __restrict__ lab_lens) {
    const int n = blockIdx.x;
    const int l = threadIdx.x;
    const bool active = l < L_DIM;

    __shared__ float alpha[L_DIM];
    __shared__ int ext[L_DIM];
    if (active) ext[l] = (l & 1) ? labeling[n * S_DIM + (l >> 1)] : 0;
    __syncthreads();
    const bool skip = active && (l >= 2) && (l & 1) && (ext[l] != ext[l - 2]);

    const float* lp_n = g_lp + (size_t)n * T_DIM * L_DIM;
    const int Tlen = in_lens[n];

    if (active) alpha[l] = (l < 2) ? lp_n[l] : NEGINF;
    __syncthreads();

    float lp_cur = active ? lp_n[L_DIM + l] : 0.f;   // t = 1
    for (int t = 1; t < Tlen; t++) {
        float lp_next = (active && (t + 1 < Tlen)) ? lp_n[(t + 1) * L_DIM + l] : 0.f;
        float nv = 0.f;
        if (active) {
            float a1 = alpha[l];
            float a2 = (l >= 1) ? alpha[l - 1] : NEGINF;
            float a3 = skip ? alpha[l - 2] : NEGINF;
            float mx = fmaxf(a1, fmaxf(a2, a3));
            float sum = expf(a1 - mx) + expf(a2 - mx) + expf(a3 - mx);
            nv = mx + logf(sum) + lp_cur;
        }
        __syncthreads();
        if (active) alpha[l] = nv;
        __syncthreads();
        lp_cur = lp_next;
    }

    if (l == 0) {
        int Ln = 2 * lab_lens[n] + 1;
        float x = alpha[Ln - 1], y = alpha[Ln - 2];
        float mx = fmaxf(x, y);
        g_nll[n] = -(mx + logf(expf(x - mx) + expf(y - mx)));
    }
}

// ---------------- K6: final sum (fixed order -> deterministic) --------------
__global__ void sum_kernel(float* __restrict__ out) {
    float s = 0.f;
    #pragma unroll
    for (int n = 0; n < N_DIM; n++) s += g_nll[n];
    out[0] = s;
}

// ---------------- launch -----------------------------------------------------
extern "C" void kernel_launch(void* const* d_in, const int* in_sizes, int n_in,
                              void* d_out, int out_size) {
    const float* feats   = (const float*)d_in[0];   // (T*N, D)
    const float* weight  = (const float*)d_in[1];   // (D, C)
    const int*   labeling = (const int*)d_in[2];    // (N, S)
    const int*   logit_lgts = (const int*)d_in[3];  // (N,)
    const int*   labeling_lgts = (const int*)d_in[4]; // (N,)
    float* out = (float*)d_out;

    col_norm_kernel<<<(C_DIM + 255) / 256, 256>>>(weight);
    row_norm_kernel<<<(T_DIM * N_DIM) / 8, 256>>>(feats);

    dim3 grid((C_DIM + BN - 1) / BN, (T_DIM * N_DIM) / BM);
    gemm_kernel<<<grid, 256>>>(feats, weight);

    lse_gather_kernel<<<T_DIM * N_DIM, 128>>>(labeling);
    ctc_kernel<<<N_DIM, 64>>>(labeling, logit_lgts, labeling_lgts);
    sum_kernel<<<1, 1>>>(out);
}

// round 4
// speedup vs baseline: 4.8522x; 4.8470x over previous
#include <cuda_runtime.h>
#include <cuda_bf16.h>
#include <cstdint>

#define NEGINF -1e9f
#define SWZ(x) ((x) ^ (((x) >> 3) & 0x70))

// ---------- device scratch (zero-initialized at load; all used cells rewritten every run) ----------
__device__ __align__(16) __nv_bfloat16 g_A[(size_t)16384 * 512];   // (t*32+n, k), 32*f/||f||
__device__ __align__(16) __nv_bfloat16 g_B[(size_t)1408 * 512];    // (c, k), w/||w||; rows>=1296 stay 0
__device__ float g_col_inv[1296];
__device__ float g_psum[(size_t)16384 * 44];
__device__ float g_gl[(size_t)32 * 512 * 32];                      // gathered logits (n,t,j)
__device__ __align__(16) float g_lp[(size_t)32 * 512 * 64];        // (n,t,l)
__device__ float g_nll[32];

__device__ __forceinline__ uint32_t sm2u(const void* p) {
    uint32_t a;
    asm("{ .reg .u64 t; cvta.to.shared.u64 t, %1; cvt.u32.u64 %0, t; }" : "=r"(a) : "l"(p));
    return a;
}
#define CPA16(d, s) asm volatile("cp.async.cg.shared.global [%0], [%1], 16;" :: "r"(d), "l"(s) : "memory")
__device__ __forceinline__ void ldmx4(uint32_t* r, uint32_t a) {
    asm volatile("ldmatrix.sync.aligned.m8n8.x4.shared.b16 {%0,%1,%2,%3}, [%4];"
        : "=r"(r[0]), "=r"(r[1]), "=r"(r[2]), "=r"(r[3]) : "r"(a));
}
__device__ __forceinline__ void mma16816(float* c, const uint32_t* a, uint32_t b0, uint32_t b1) {
    asm volatile("mma.sync.aligned.m16n8k16.row.col.f32.bf16.bf16.f32 "
        "{%0,%1,%2,%3},{%4,%5,%6,%7},{%8,%9},{%0,%1,%2,%3};"
        : "+f"(c[0]), "+f"(c[1]), "+f"(c[2]), "+f"(c[3])
        : "r"(a[0]), "r"(a[1]), "r"(a[2]), "r"(a[3]), "r"(b0), "r"(b1));
}
__device__ __forceinline__ float bflo(uint32_t u) { return __uint_as_float(u << 16); }
__device__ __forceinline__ float bfhi(uint32_t u) { return __uint_as_float(u & 0xffff0000u); }

// ---------- K1: column inverse norms ----------
__global__ void col_norm_kernel(const float* __restrict__ w) {
    int c = blockIdx.x * blockDim.x + threadIdx.x;
    if (c >= 1296) return;
    float s = 0.f;
    #pragma unroll 4
    for (int d = 0; d < 512; d++) { float v = w[(size_t)d * 1296 + c]; s += v * v; }
    g_col_inv[c] = rsqrtf(s);
}

// ---------- K2: W transpose + normalize -> bf16 (c,k) ----------
__global__ void wtrans_kernel(const float* __restrict__ w) {
    __shared__ float tile[32][33];
    int c0 = blockIdx.x * 32, k0 = blockIdx.y * 32;
    int tx = threadIdx.x, ty = threadIdx.y;
    #pragma unroll
    for (int i = 0; i < 4; i++) {
        int c = c0 + tx, k = k0 + ty + i * 8;
        tile[ty + i * 8][tx] = (c < 1296) ? w[(size_t)k * 1296 + c] : 0.f;
    }
    __syncthreads();
    #pragma unroll
    for (int i = 0; i < 4; i++) {
        int c = c0 + ty + i * 8, k = k0 + tx;
        if (c < 1296)
            g_B[(size_t)c * 512 + k] = __float2bfloat16(tile[tx][ty + i * 8] * g_col_inv[c]);
    }
}

// ---------- K3: feats * 32/||f|| -> bf16 ----------
__global__ void fprep_kernel(const float* __restrict__ f) {
    int gw = (blockIdx.x * blockDim.x + threadIdx.x) >> 5;
    int lane = threadIdx.x & 31;
    if (gw >= 16384) return;
    const float2* row = (const float2*)(f + (size_t)gw * 512);
    float2 v[8]; float s = 0.f;
    #pragma unroll
    for (int j = 0; j < 8; j++) { v[j] = row[j * 32 + lane]; s += v[j].x * v[j].x + v[j].y * v[j].y; }
    #pragma unroll
    for (int o = 16; o > 0; o >>= 1) s += __shfl_xor_sync(0xffffffffu, s, o);
    float sc = 32.f * rsqrtf(s);
    __nv_bfloat162* dst = (__nv_bfloat162*)(g_A + (size_t)gw * 512);
    #pragma unroll
    for (int j = 0; j < 8; j++) dst[j * 32 + lane] = __floats2bfloat162_rn(v[j].x * sc, v[j].y * sc);
}

// ---------- K4: HMMA GEMM + fused exp-sum epilogue ----------
__device__ __forceinline__ void load_stage(uint32_t sb, int st, int m0, int c0, int kc, int tid) {
    uint32_t abase = sb + (unsigned)st * 32768u;
    uint32_t bbase = abase + 16384u;
    #pragma unroll
    for (int it = 0; it < 8; it++) {
        int i = tid + it * 256;
        int row = i >> 3, ch = i & 7;
        uint32_t off = SWZ((uint32_t)((row & 127) * 128 + ch * 16));
        const char* src;
        uint32_t dst;
        if (row < 128) {
            src = (const char*)(g_A + ((size_t)(m0 + row)) * 512 + kc * 64) + ch * 16;
            dst = abase + off;
        } else {
            src = (const char*)(g_B + ((size_t)(c0 + row - 128)) * 512 + kc * 64) + ch * 16;
            dst = bbase + off;
        }
        CPA16(dst, src);
    }
    asm volatile("cp.async.commit_group;" ::: "memory");
}

__global__ void __launch_bounds__(256) gemm_kernel() {
    extern __shared__ __align__(128) char smem[];
    uint32_t sb = sm2u(smem);
    const int tid = threadIdx.x;
    const int lane = tid & 31, w = tid >> 5;
    const int warp_m = w >> 2, warp_n = w & 3;
    const int m0 = blockIdx.y * 128, c0 = blockIdx.x * 128;

    float acc[4][4][4];
    #pragma unroll
    for (int i = 0; i < 4; i++)
        #pragma unroll
        for (int j = 0; j < 4; j++)
            #pragma unroll
            for (int q = 0; q < 4; q++) acc[i][j][q] = 0.f;

    // per-lane ldmatrix base addresses (swizzle xor folded in)
    const int rowA = warp_m * 64 + (lane & 15);
    const uint32_t aBase0 = (uint32_t)(rowA * 128) + ((((lane >> 4) ^ lane) & 1) << 4);
    const int rowB = warp_n * 32 + (lane & 7) + (((lane >> 4) & 1) << 3);
    const uint32_t bBase0 = (uint32_t)(rowB * 128) + ((((lane >> 3) ^ lane) & 1) << 4);
    const uint32_t kx = (uint32_t)(lane & 6) << 4;

    load_stage(sb, 0, m0, c0, 0, tid);

    for (int kc = 0; kc < 8; kc++) {
        if (kc < 7) {
            load_stage(sb, (kc + 1) & 1, m0, c0, kc + 1, tid);
            asm volatile("cp.async.wait_group 1;" ::: "memory");
        } else {
            asm volatile("cp.async.wait_group 0;" ::: "memory");
        }
        __syncthreads();
        uint32_t astage = sb + (unsigned)(kc & 1) * 32768u;
        uint32_t bstage = astage + 16384u;
        #pragma unroll
        for (int ks = 0; ks < 4; ks++) {
            uint32_t ko = ((uint32_t)(ks << 5)) ^ kx;
            uint32_t a[4][4], bfr[8];
            #pragma unroll
            for (int mi = 0; mi < 4; mi++)
                ldmx4(a[mi], astage + aBase0 + mi * 2048 + ko);
            ldmx4(&bfr[0], bstage + bBase0 + ko);
            ldmx4(&bfr[4], bstage + bBase0 + 2048 + ko);
            #pragma unroll
            for (int mi = 0; mi < 4; mi++)
                #pragma unroll
                for (int nj = 0; nj < 4; nj++)
                    mma16816(acc[mi][nj], a[mi], bfr[nj * 2], bfr[nj * 2 + 1]);
        }
        __syncthreads();
    }

    // epilogue: sum of exp(x-32) per row, quad-reduce over n, store partials
    const int tq = lane >> 2, qi = lane & 3;
    #pragma unroll
    for (int mi = 0; mi < 4; mi++) {
        #pragma unroll
        for (int half = 0; half < 2; half++) {
            float s = 0.f;
            #pragma unroll
            for (int nj = 0; nj < 4; nj++) {
                int c = c0 + warp_n * 32 + nj * 8 + qi * 2;
                float x0 = acc[mi][nj][half * 2 + 0];
                float x1 = acc[mi][nj][half * 2 + 1];
                if (c < 1296)     s += __expf(x0 - 32.f);
                if (c + 1 < 1296) s += __expf(x1 - 32.f);
            }
            s += __shfl_xor_sync(0xffffffffu, s, 1);
            s += __shfl_xor_sync(0xffffffffu, s, 2);
            if (qi == 0) {
                int m = m0 + warp_m * 64 + mi * 16 + tq + half * 8;
                g_psum[(size_t)m * 44 + blockIdx.x * 4 + warp_n] = s;
            }
        }
    }
}

// ---------- K5: gather GEMM (31 needed columns per sequence) ----------
__global__ void __launch_bounds__(256) gather_kernel(const int* __restrict__ labeling) {
    __shared__ __nv_bfloat16 sB[32][516];
    const int n = blockIdx.x, t0 = blockIdx.y * 32;
    const int tid = threadIdx.x;
    for (int i = tid; i < 31 * 128; i += 256) {      // 8B chunks
        int j = i >> 7, ch = i & 127;
        int col = (j == 0) ? 0 : labeling[n * 30 + j - 1];
        *(uint2*)&sB[j][ch * 4] = *(const uint2*)(g_B + (size_t)col * 512 + ch * 4);
    }
    __syncthreads();
    const int w = tid >> 5, lane = tid & 31;
    if (lane >= 31) return;
    #pragma unroll
    for (int rr = 0; rr < 4; rr++) {
        int t = t0 + w * 4 + rr;
        const uint2* a2 = (const uint2*)(g_A + ((size_t)t * 32 + n) * 512);
        const uint2* b2 = (const uint2*)&sB[lane][0];
        float s = 0.f;
        #pragma unroll 8
        for (int i = 0; i < 128; i++) {
            uint2 av = a2[i], bv = b2[i];
            s += bflo(av.x) * bflo(bv.x) + bfhi(av.x) * bfhi(bv.x)
               + bflo(av.y) * bflo(bv.y) + bfhi(av.y) * bfhi(bv.y);
        }
        g_gl[((size_t)n * 512 + t) * 32 + lane] = s;
    }
}

// ---------- K6: finalize lp ----------
__global__ void finalize_kernel() {
    int gw = blockIdx.x * 8 + (threadIdx.x >> 5);
    int lane = threadIdx.x & 31;
    int n = gw >> 9, t = gw & 511;
    const float* P = g_psum + ((size_t)t * 32 + n) * 44;
    float p = (lane < 22) ? (P[lane] + P[lane + 22]) : 0.f;
    #pragma unroll
    for (int o = 16; o > 0; o >>= 1) p += __shfl_xor_sync(0xffffffffu, p, o);
    float lse = 32.f + logf(p);
    const float* G = g_gl + ((size_t)n * 512 + t) * 32;
    float2* dst = (float2*)g_lp + ((size_t)n * 512 + t) * 32;
    float g0 = G[0];
    float2 v;
    if (lane < 30)       v = make_float2(g0 - lse, G[1 + lane] - lse);
    else if (lane == 30) v = make_float2(g0 - lse, NEGINF);
    else                 v = make_float2(NEGINF, NEGINF);
    dst[lane] = v;
}

// ---------- K7: CTC, one warp per sequence, 2 states per lane ----------
__global__ void ctc_kernel(const int* __restrict__ labeling,
                           const int* __restrict__ in_lens,
                           const int* __restrict__ lab_lens) {
    const int n = blockIdx.x;
    const int l = threadIdx.x;
    int labv = (l < 30) ? labeling[n * 30 + l] : 0;
    int labp = (l >= 1 && l <= 30) ? labeling[n * 30 + l - 1] : 0;
    const bool skip = (l >= 1 && l <= 29 && labv != labp);
    const int Tlen = in_lens[n];

    const float2* base2 = (const float2*)g_lp + (size_t)n * 512 * 32 + l;
    float2 v0 = base2[0];
    float lo = (l == 0) ? v0.x : NEGINF;
    float hi = (l == 0) ? v0.y : NEGINF;
    float2 lp = base2[32];
    for (int t = 1; t < Tlen; t++) {
        float2 nxt = (t + 1 < Tlen) ? base2[(size_t)(t + 1) * 32] : make_float2(0.f, 0.f);
        float hp = __shfl_up_sync(0xffffffffu, hi, 1);
        if (l == 0) hp = NEGINF;
        float m1 = fmaxf(lo, hp);
        float nlo = m1 + __logf(__expf(lo - m1) + __expf(hp - m1)) + lp.x;
        float a3 = skip ? hp : NEGINF;
        float m2 = fmaxf(hi, fmaxf(lo, a3));
        float nhi = m2 + __logf(__expf(hi - m2) + __expf(lo - m2) + __expf(a3 - m2)) + lp.y;
        lo = nlo; hi = nhi; lp = nxt;
    }
    int lab = lab_lens[n];
    float x = __shfl_sync(0xffffffffu, lo, lab);
    float y = __shfl_sync(0xffffffffu, hi, lab - 1);
    if (l == 0) {
        float mx = fmaxf(x, y);
        g_nll[n] = -(mx + logf(expf(x - mx) + expf(y - mx)));
    }
}

// ---------- K8: deterministic sum ----------
__global__ void sum_kernel(float* __restrict__ out) {
    float s = 0.f;
    #pragma unroll
    for (int n = 0; n < 32; n++) s += g_nll[n];
    out[0] = s;
}

// ---------- launch ----------
extern "C" void kernel_launch(void* const* d_in, const int* in_sizes, int n_in,
                              void* d_out, int out_size) {
    const float* feats = (const float*)d_in[0];
    const float* weight = (const float*)d_in[1];
    const int* labeling = (const int*)d_in[2];
    const int* logit_lgts = (const int*)d_in[3];
    const int* labeling_lgts = (const int*)d_in[4];
    float* out = (float*)d_out;

    cudaFuncSetAttribute(gemm_kernel, cudaFuncAttributeMaxDynamicSharedMemorySize, 65536);

    col_norm_kernel<<<(1296 + 255) / 256, 256>>>(weight);
    wtrans_kernel<<<dim3(41, 16), dim3(32, 8)>>>(weight);
    fprep_kernel<<<2048, 256>>>(feats);
    gemm_kernel<<<dim3(11, 128), 256, 65536>>>();
    gather_kernel<<<dim3(32, 16), 256>>>(labeling);
    finalize_kernel<<<2048, 256>>>();
    ctc_kernel<<<32, 32>>>(labeling, logit_lgts, labeling_lgts);
    sum_kernel<<<1, 1>>>(out);
}

// round 5
// speedup vs baseline: 5.3101x; 1.0944x over previous
#include <cuda_runtime.h>
#include <cuda_bf16.h>
#include <cstdint>

#define NEGINF -1e9f
#define SWZ(x) ((x) ^ (((x) >> 3) & 0x70))

// ---------- device scratch ----------
__device__ __align__(16) __nv_bfloat16 g_A[(size_t)16384 * 512];   // (t*32+n, k), 32*f/||f||
__device__ __align__(16) __nv_bfloat16 g_B[(size_t)1408 * 512];    // (c, k); rows>=1296 stay 0
__device__ float   g_col_inv[1296];
__device__ uint8_t g_colmap[32 * 1296];                            // value -> state slot + 1
__device__ float   g_psum[(size_t)16384 * 44];
__device__ float   g_lpraw[(size_t)16384 * 64];                    // gathered logits by slot
__device__ __align__(16) float g_lp[(size_t)32 * 512 * 64];        // (n,t,l)
__device__ float   g_nll[32];

__device__ __forceinline__ uint32_t sm2u(const void* p) {
    uint32_t a;
    asm("{ .reg .u64 t; cvta.to.shared.u64 t, %1; cvt.u32.u64 %0, t; }" : "=r"(a) : "l"(p));
    return a;
}
#define CPA16(d, s) asm volatile("cp.async.cg.shared.global [%0], [%1], 16;" :: "r"(d), "l"(s) : "memory")
__device__ __forceinline__ void ldmx4(uint32_t* r, uint32_t a) {
    asm volatile("ldmatrix.sync.aligned.m8n8.x4.shared.b16 {%0,%1,%2,%3}, [%4];"
        : "=r"(r[0]), "=r"(r[1]), "=r"(r[2]), "=r"(r[3]) : "r"(a));
}
__device__ __forceinline__ void mma16816(float* c, const uint32_t* a, uint32_t b0, uint32_t b1) {
    asm volatile("mma.sync.aligned.m16n8k16.row.col.f32.bf16.bf16.f32 "
        "{%0,%1,%2,%3},{%4,%5,%6,%7},{%8,%9},{%0,%1,%2,%3};"
        : "+f"(c[0]), "+f"(c[1]), "+f"(c[2]), "+f"(c[3])
        : "r"(a[0]), "r"(a[1]), "r"(a[2]), "r"(a[3]), "r"(b0), "r"(b1));
}

// ---------- K1: column inverse norms ----------
__global__ void col_norm_kernel(const float* __restrict__ w) {
    int c = blockIdx.x * blockDim.x + threadIdx.x;
    if (c >= 1296) return;
    float s = 0.f;
    #pragma unroll 4
    for (int d = 0; d < 512; d++) { float v = w[(size_t)d * 1296 + c]; s += v * v; }
    g_col_inv[c] = rsqrtf(s);
}

// ---------- K2: W transpose + normalize -> bf16 (c,k) ----------
__global__ void wtrans_kernel(const float* __restrict__ w) {
    __shared__ float tile[32][33];
    int c0 = blockIdx.x * 32, k0 = blockIdx.y * 32;
    int tx = threadIdx.x, ty = threadIdx.y;
    #pragma unroll
    for (int i = 0; i < 4; i++) {
        int c = c0 + tx, k = k0 + ty + i * 8;
        tile[ty + i * 8][tx] = (c < 1296) ? w[(size_t)k * 1296 + c] : 0.f;
    }
    __syncthreads();
    #pragma unroll
    for (int i = 0; i < 4; i++) {
        int c = c0 + ty + i * 8, k = k0 + tx;
        if (c < 1296)
            g_B[(size_t)c * 512 + k] = __float2bfloat16(tile[tx][ty + i * 8] * g_col_inv[c]);
    }
}

// ---------- K3: feats * 32/||f|| -> bf16 ----------
__global__ void fprep_kernel(const float* __restrict__ f) {
    int gw = (blockIdx.x * blockDim.x + threadIdx.x) >> 5;
    int lane = threadIdx.x & 31;
    if (gw >= 16384) return;
    const float2* row = (const float2*)(f + (size_t)gw * 512);
    float2 v[8]; float s = 0.f;
    #pragma unroll
    for (int j = 0; j < 8; j++) { v[j] = row[j * 32 + lane]; s += v[j].x * v[j].x + v[j].y * v[j].y; }
    #pragma unroll
    for (int o = 16; o > 0; o >>= 1) s += __shfl_xor_sync(0xffffffffu, s, o);
    float sc = 32.f * rsqrtf(s);
    __nv_bfloat162* dst = (__nv_bfloat162*)(g_A + (size_t)gw * 512);
    #pragma unroll
    for (int j = 0; j < 8; j++) dst[j * 32 + lane] = __floats2bfloat162_rn(v[j].x * sc, v[j].y * sc);
}

// ---------- K4: colmap (col value -> state slot + 1, per sequence) ----------
__global__ void colmap_kernel(const int* __restrict__ labeling) {
    int tid = threadIdx.x;
    for (int i = tid; i < 32 * 1296 / 4; i += 256) ((uint32_t*)g_colmap)[i] = 0;
    __syncthreads();
    if (tid < 32) {
        uint8_t* row = g_colmap + tid * 1296;
        row[0] = 1;
        for (int l = 1; l < 61; l += 2) row[labeling[tid * 30 + (l >> 1)]] = (uint8_t)(l + 1);
    }
}

// ---------- K5: HMMA GEMM + fused exp-sum / gather epilogue ----------
__device__ __forceinline__ void load_stage(uint32_t sb, int st, int m0, int c0, int kc, int tid) {
    uint32_t abase = sb + (unsigned)st * 32768u;
    uint32_t bbase = abase + 16384u;
    #pragma unroll
    for (int it = 0; it < 8; it++) {
        int i = tid + it * 256;
        int row = i >> 3, ch = i & 7;
        uint32_t off = SWZ((uint32_t)((row & 127) * 128 + ch * 16));
        const char* src;
        uint32_t dst;
        if (row < 128) {
            src = (const char*)(g_A + ((size_t)(m0 + row)) * 512 + kc * 64) + ch * 16;
            dst = abase + off;
        } else {
            src = (const char*)(g_B + ((size_t)(c0 + row - 128)) * 512 + kc * 64) + ch * 16;
            dst = bbase + off;
        }
        CPA16(dst, src);
    }
    asm volatile("cp.async.commit_group;" ::: "memory");
}

__global__ void __launch_bounds__(256) gemm_kernel() {
    extern __shared__ __align__(128) char smem[];
    uint32_t sb = sm2u(smem);
    const int tid = threadIdx.x;
    const int lane = tid & 31, w = tid >> 5;
    const int warp_m = w >> 2, warp_n = w & 3;
    const int m0 = blockIdx.y * 128, c0 = blockIdx.x * 128;

    float acc[4][4][4];
    #pragma unroll
    for (int i = 0; i < 4; i++)
        #pragma unroll
        for (int j = 0; j < 4; j++)
            #pragma unroll
            for (int q = 0; q < 4; q++) acc[i][j][q] = 0.f;

    const int rowA = warp_m * 64 + (lane & 15);
    const uint32_t aBase0 = (uint32_t)(rowA * 128) + ((((lane >> 4) ^ lane) & 1) << 4);
    const int rowB = warp_n * 32 + (lane & 7) + (((lane >> 4) & 1) << 3);
    const uint32_t bBase0 = (uint32_t)(rowB * 128) + ((((lane >> 3) ^ lane) & 1) << 4);
    const uint32_t kx = (uint32_t)(lane & 6) << 4;

    load_stage(sb, 0, m0, c0, 0, tid);
    load_stage(sb, 1, m0, c0, 1, tid);

    #pragma unroll 1
    for (int kc = 0; kc < 8; kc++) {
        if (kc < 7) asm volatile("cp.async.wait_group 1;" ::: "memory");
        else        asm volatile("cp.async.wait_group 0;" ::: "memory");
        __syncthreads();
        uint32_t astage = sb + (unsigned)(kc % 3) * 32768u;
        uint32_t bstage = astage + 16384u;
        #pragma unroll
        for (int ks = 0; ks < 4; ks++) {
            uint32_t ko = ((uint32_t)(ks << 5)) ^ kx;
            uint32_t a[4][4], bfr[8];
            #pragma unroll
            for (int mi = 0; mi < 4; mi++)
                ldmx4(a[mi], astage + aBase0 + mi * 2048 + ko);
            ldmx4(&bfr[0], bstage + bBase0 + ko);
            ldmx4(&bfr[4], bstage + bBase0 + 2048 + ko);
            #pragma unroll
            for (int mi = 0; mi < 4; mi++)
                #pragma unroll
                for (int nj = 0; nj < 4; nj++)
                    mma16816(acc[mi][nj], a[mi], bfr[nj * 2], bfr[nj * 2 + 1]);
        }
        if (kc < 6) load_stage(sb, (kc + 2) % 3, m0, c0, kc + 2, tid);
    }

    // epilogue: per-row sum of exp(x-32) + gather of labeled columns
    const int tq = lane >> 2, qi = lane & 3;
    #pragma unroll
    for (int mi = 0; mi < 4; mi++) {
        #pragma unroll
        for (int half = 0; half < 2; half++) {
            int m = m0 + warp_m * 64 + mi * 16 + tq + half * 8;
            const uint8_t* cm = g_colmap + (size_t)(m & 31) * 1296;
            float s = 0.f;
            #pragma unroll
            for (int nj = 0; nj < 4; nj++) {
                int c = c0 + warp_n * 32 + nj * 8 + qi * 2;
                float x0 = acc[mi][nj][half * 2 + 0];
                float x1 = acc[mi][nj][half * 2 + 1];
                if (c < 1296) {
                    s += __expf(x0 - 32.f);
                    uint8_t v = cm[c];
                    if (v) g_lpraw[(size_t)m * 64 + v - 1] = x0;
                }
                if (c + 1 < 1296) {
                    s += __expf(x1 - 32.f);
                    uint8_t v = cm[c + 1];
                    if (v) g_lpraw[(size_t)m * 64 + v - 1] = x1;
                }
            }
            s += __shfl_xor_sync(0xffffffffu, s, 1);
            s += __shfl_xor_sync(0xffffffffu, s, 2);
            if (qi == 0)
                g_psum[(size_t)m * 44 + blockIdx.x * 4 + warp_n] = s;
        }
    }
}

// ---------- K6: finalize lp = gathered - lse ----------
__global__ void finalize_kernel(const int* __restrict__ labeling) {
    int gw = blockIdx.x * 8 + (threadIdx.x >> 5);   // gw = t*32 + n
    int lane = threadIdx.x & 31;
    int t = gw >> 5, n = gw & 31;
    const float* P = g_psum + (size_t)gw * 44;
    float p = (lane < 22) ? (P[lane] + P[lane + 22]) : 0.f;
    #pragma unroll
    for (int o = 16; o > 0; o >>= 1) p += __shfl_xor_sync(0xffffffffu, p, o);
    float lse = 32.f + logf(p);
    float* dst = g_lp + ((size_t)n * 512 + t) * 64;
    const float* raw = g_lpraw + (size_t)gw * 64;
    #pragma unroll
    for (int r = 0; r < 2; r++) {
        int l = lane + r * 32;
        if (l < 61) {
            int ext = (l & 1) ? labeling[n * 30 + (l >> 1)] : 0;
            int v = g_colmap[n * 1296 + ext];
            dst[l] = raw[v - 1] - lse;
        } else if (l < 64) dst[l] = NEGINF;
    }
}

// ---------- K7: CTC, one warp per sequence, 2 states per lane ----------
__global__ void ctc_kernel(const int* __restrict__ labeling,
                           const int* __restrict__ in_lens,
                           const int* __restrict__ lab_lens) {
    const int n = blockIdx.x;
    const int l = threadIdx.x;
    int labv = (l < 30) ? labeling[n * 30 + l] : 0;
    int labp = (l >= 1 && l <= 30) ? labeling[n * 30 + l - 1] : 0;
    const bool skip = (l >= 1 && l <= 29 && labv != labp);
    const int Tlen = in_lens[n];

    const float2* base2 = (const float2*)g_lp + (size_t)n * 512 * 32 + l;
    float2 v0 = base2[0];
    float lo = (l == 0) ? v0.x : NEGINF;
    float hi = (l == 0) ? v0.y : NEGINF;
    float2 lp = base2[32];
    for (int t = 1; t < Tlen; t++) {
        float2 nxt = (t + 1 < Tlen) ? base2[(size_t)(t + 1) * 32] : make_float2(0.f, 0.f);
        float hp = __shfl_up_sync(0xffffffffu, hi, 1);
        if (l == 0) hp = NEGINF;
        float m1 = fmaxf(lo, hp);
        float nlo = m1 + __logf(__expf(lo - m1) + __expf(hp - m1)) + lp.x;
        float a3 = skip ? hp : NEGINF;
        float m2 = fmaxf(hi, fmaxf(lo, a3));
        float nhi = m2 + __logf(__expf(hi - m2) + __expf(lo - m2) + __expf(a3 - m2)) + lp.y;
        lo = nlo; hi = nhi; lp = nxt;
    }
    int lab = lab_lens[n];
    float x = __shfl_sync(0xffffffffu, lo, lab);
    float y = __shfl_sync(0xffffffffu, hi, lab - 1);
    if (l == 0) {
        float mx = fmaxf(x, y);
        g_nll[n] = -(mx + logf(expf(x - mx) + expf(y - mx)));
    }
}

// ---------- K8: deterministic sum ----------
__global__ void sum_kernel(float* __restrict__ out) {
    float s = 0.f;
    #pragma unroll
    for (int n = 0; n < 32; n++) s += g_nll[n];
    out[0] = s;
}

// ---------- launch ----------
extern "C" void kernel_launch(void* const* d_in, const int* in_sizes, int n_in,
                              void* d_out, int out_size) {
    const float* feats = (const float*)d_in[0];
    const float* weight = (const float*)d_in[1];
    const int* labeling = (const int*)d_in[2];
    const int* logit_lgts = (const int*)d_in[3];
    const int* labeling_lgts = (const int*)d_in[4];
    float* out = (float*)d_out;

    cudaFuncSetAttribute(gemm_kernel, cudaFuncAttributeMaxDynamicSharedMemorySize, 98304);

    col_norm_kernel<<<(1296 + 255) / 256, 256>>>(weight);
    wtrans_kernel<<<dim3(41, 16), dim3(32, 8)>>>(weight);
    fprep_kernel<<<2048, 256>>>(feats);
    colmap_kernel<<<1, 256>>>(labeling);
    gemm_kernel<<<dim3(11, 128), 256, 98304>>>();
    finalize_kernel<<<2048, 256>>>(labeling);
    ctc_kernel<<<32, 32>>>(labeling, logit_lgts, labeling_lgts);
    sum_kernel<<<1, 1>>>(out);
}

// round 7
// speedup vs baseline: 6.8769x; 1.2951x over previous
#include <cuda_runtime.h>
#include <cuda_bf16.h>
#include <cstdint>

#define NEGINF -1e9f
#define SWZ(x) ((x) ^ (((x) >> 3) & 0x70))

// ---------- device scratch ----------
__device__ __align__(16) __nv_bfloat16 g_A[(size_t)16384 * 512];   // (t*32+n, k), 32*f/||f||
__device__ __align__(16) __nv_bfloat16 g_B[(size_t)1408 * 512];    // (c, k); rows>=1296 stay 0
__device__ float   g_part[8 * 1296];                               // col sum-of-squares partials
__device__ uint8_t g_colmap[32 * 1296];                            // value -> state slot + 1
__device__ float   g_psum[(size_t)16384 * 44];
__device__ float   g_lpraw[(size_t)16384 * 64];                    // gathered logits by slot
__device__ __align__(16) float g_lp[(size_t)32 * 512 * 64];        // (n,t,l) log-probs
__device__ float   g_nll[32];

__device__ __forceinline__ uint32_t sm2u(const void* p) {
    uint32_t a;
    asm("{ .reg .u64 t; cvta.to.shared.u64 t, %1; cvt.u32.u64 %0, t; }" : "=r"(a) : "l"(p));
    return a;
}
#define CPA16(d, s) asm volatile("cp.async.cg.shared.global [%0], [%1], 16;" :: "r"(d), "l"(s) : "memory")
__device__ __forceinline__ void ldmx4(uint32_t* r, uint32_t a) {
    asm volatile("ldmatrix.sync.aligned.m8n8.x4.shared.b16 {%0,%1,%2,%3}, [%4];"
        : "=r"(r[0]), "=r"(r[1]), "=r"(r[2]), "=r"(r[3]) : "r"(a));
}
__device__ __forceinline__ void mma16816(float* c, const uint32_t* a, uint32_t b0, uint32_t b1) {
    asm volatile("mma.sync.aligned.m16n8k16.row.col.f32.bf16.bf16.f32 "
        "{%0,%1,%2,%3},{%4,%5,%6,%7},{%8,%9},{%0,%1,%2,%3};"
        : "+f"(c[0]), "+f"(c[1]), "+f"(c[2]), "+f"(c[3])
        : "r"(a[0]), "r"(a[1]), "r"(a[2]), "r"(a[3]), "r"(b0), "r"(b1));
}

// ---------- K1: column sum-of-squares partials (full-chip, coalesced) --------
__global__ void colsum_kernel(const float* __restrict__ w) {
    __shared__ float sp[8][33];
    int c0 = blockIdx.x * 32, d0 = blockIdx.y * 64;
    int tx = threadIdx.x, ty = threadIdx.y;      // (32, 8)
    int c = c0 + tx;
    float s = 0.f;
    if (c < 1296) {
        #pragma unroll
        for (int i = 0; i < 8; i++) {
            float v = w[(size_t)(d0 + ty + i * 8) * 1296 + c];
            s += v * v;
        }
    }
    sp[ty][tx] = s;
    __syncthreads();
    if (ty == 0 && c < 1296) {
        float t = 0.f;
        #pragma unroll
        for (int i = 0; i < 8; i++) t += sp[i][tx];
        g_part[blockIdx.y * 1296 + c] = t;
    }
}

// ---------- K2: W transpose + normalize -> bf16 (c,k) ----------
__global__ void wtrans_kernel(const float* __restrict__ w) {
    __shared__ float tile[32][33];
    int c0 = blockIdx.x * 32, k0 = blockIdx.y * 32;
    int tx = threadIdx.x, ty = threadIdx.y;
    #pragma unroll
    for (int i = 0; i < 4; i++) {
        int c = c0 + tx, k = k0 + ty + i * 8;
        tile[ty + i * 8][tx] = (c < 1296) ? w[(size_t)k * 1296 + c] : 0.f;
    }
    __syncthreads();
    #pragma unroll
    for (int i = 0; i < 4; i++) {
        int c = c0 + ty + i * 8, k = k0 + tx;
        if (c < 1296) {
            float sum = 0.f;
            #pragma unroll
            for (int j = 0; j < 8; j++) sum += g_part[j * 1296 + c];
            g_B[(size_t)c * 512 + k] = __float2bfloat16(tile[tx][ty + i * 8] * rsqrtf(sum));
        }
    }
}

// ---------- K3: feats * 32/||f|| -> bf16 ; blocks 0-31 also build colmap ----
__global__ void fprep_kernel(const float* __restrict__ f, const int* __restrict__ labeling) {
    int gw = (blockIdx.x * blockDim.x + threadIdx.x) >> 5;
    int lane = threadIdx.x & 31;
    const float2* row = (const float2*)(f + (size_t)gw * 512);
    float2 v[8]; float s = 0.f;
    #pragma unroll
    for (int j = 0; j < 8; j++) { v[j] = row[j * 32 + lane]; s += v[j].x * v[j].x + v[j].y * v[j].y; }
    #pragma unroll
    for (int o = 16; o > 0; o >>= 1) s += __shfl_xor_sync(0xffffffffu, s, o);
    float sc = 32.f * rsqrtf(s);
    __nv_bfloat162* dst = (__nv_bfloat162*)(g_A + (size_t)gw * 512);
    #pragma unroll
    for (int j = 0; j < 8; j++) dst[j * 32 + lane] = __floats2bfloat162_rn(v[j].x * sc, v[j].y * sc);

    if (blockIdx.x < 32) {
        int n = blockIdx.x;
        uint32_t* row32 = (uint32_t*)(g_colmap + n * 1296);
        for (int i = threadIdx.x; i < 324; i += 256) row32[i] = 0;
        __syncthreads();
        if (threadIdx.x == 0) {
            uint8_t* r8 = g_colmap + n * 1296;
            r8[0] = 1;
            for (int l = 1; l < 61; l += 2) r8[labeling[n * 30 + (l >> 1)]] = (uint8_t)(l + 1);
        }
    }
}

// ---------- K4: HMMA GEMM + fused exp-sum / gather epilogue ----------
__device__ __forceinline__ void load_stage(uint32_t sb, int st, int m0, int c0, int kc, int tid) {
    uint32_t abase = sb + (unsigned)st * 32768u;
    uint32_t bbase = abase + 16384u;
    #pragma unroll
    for (int it = 0; it < 8; it++) {
        int i = tid + it * 256;
        int row = i >> 3, ch = i & 7;
        uint32_t off = SWZ((uint32_t)((row & 127) * 128 + ch * 16));
        const char* src;
        uint32_t dst;
        if (row < 128) {
            src = (const char*)(g_A + ((size_t)(m0 + row)) * 512 + kc * 64) + ch * 16;
            dst = abase + off;
        } else {
            src = (const char*)(g_B + ((size_t)(c0 + row - 128)) * 512 + kc * 64) + ch * 16;
            dst = bbase + off;
        }
        CPA16(dst, src);
    }
    asm volatile("cp.async.commit_group;" ::: "memory");
}

__global__ void __launch_bounds__(256) gemm_kernel() {
    extern __shared__ __align__(128) char smem[];
    uint32_t sb = sm2u(smem);
    const int tid = threadIdx.x;
    const int lane = tid & 31, w = tid >> 5;
    const int warp_m = w >> 2, warp_n = w & 3;
    const int m0 = blockIdx.y * 128, c0 = blockIdx.x * 128;

    float acc[4][4][4];
    #pragma unroll
    for (int i = 0; i < 4; i++)
        #pragma unroll
        for (int j = 0; j < 4; j++)
            #pragma unroll
            for (int q = 0; q < 4; q++) acc[i][j][q] = 0.f;

    const int rowA = warp_m * 64 + (lane & 15);
    const uint32_t aBase0 = (uint32_t)(rowA * 128) + ((((lane >> 4) ^ lane) & 1) << 4);
    const int rowB = warp_n * 32 + (lane & 7) + (((lane >> 4) & 1) << 3);
    const uint32_t bBase0 = (uint32_t)(rowB * 128) + ((((lane >> 3) ^ lane) & 1) << 4);
    const uint32_t kx = (uint32_t)(lane & 6) << 4;

    load_stage(sb, 0, m0, c0, 0, tid);
    load_stage(sb, 1, m0, c0, 1, tid);

    #pragma unroll 1
    for (int kc = 0; kc < 8; kc++) {
        if (kc < 7) asm volatile("cp.async.wait_group 1;" ::: "memory");
        else        asm volatile("cp.async.wait_group 0;" ::: "memory");
        __syncthreads();
        if (kc < 6) load_stage(sb, (kc + 2) % 3, m0, c0, kc + 2, tid);
        uint32_t astage = sb + (unsigned)(kc % 3) * 32768u;
        uint32_t bstage = astage + 16384u;
        #pragma unroll
        for (int ks = 0; ks < 4; ks++) {
            uint32_t ko = ((uint32_t)(ks << 5)) ^ kx;
            uint32_t a[4][4], bfr[8];
            #pragma unroll
            for (int mi = 0; mi < 4; mi++)
                ldmx4(a[mi], astage + aBase0 + mi * 2048 + ko);
            ldmx4(&bfr[0], bstage + bBase0 + ko);
            ldmx4(&bfr[4], bstage + bBase0 + 2048 + ko);
            #pragma unroll
            for (int mi = 0; mi < 4; mi++)
                #pragma unroll
                for (int nj = 0; nj < 4; nj++)
                    mma16816(acc[mi][nj], a[mi], bfr[nj * 2], bfr[nj * 2 + 1]);
        }
    }

    const int tq = lane >> 2, qi = lane & 3;
    #pragma unroll
    for (int mi = 0; mi < 4; mi++) {
        #pragma unroll
        for (int half = 0; half < 2; half++) {
            int m = m0 + warp_m * 64 + mi * 16 + tq + half * 8;
            const uint8_t* cm = g_colmap + (size_t)(m & 31) * 1296;
            float s = 0.f;
            #pragma unroll
            for (int nj = 0; nj < 4; nj++) {
                int c = c0 + warp_n * 32 + nj * 8 + qi * 2;
                float x0 = acc[mi][nj][half * 2 + 0];
                float x1 = acc[mi][nj][half * 2 + 1];
                if (c < 1296) {
                    s += __expf(x0 - 32.f);
                    uint8_t v = cm[c];
                    if (v) g_lpraw[(size_t)m * 64 + v - 1] = x0;
                }
                if (c + 1 < 1296) {
                    s += __expf(x1 - 32.f);
                    uint8_t v = cm[c + 1];
                    if (v) g_lpraw[(size_t)m * 64 + v - 1] = x1;
                }
            }
            s += __shfl_xor_sync(0xffffffffu, s, 1);
            s += __shfl_xor_sync(0xffffffffu, s, 2);
            if (qi == 0)
                g_psum[(size_t)m * 44 + blockIdx.x * 4 + warp_n] = s;
        }
    }
}

// ---------- K5: finalize lp = gathered - lse (log domain) ----------
__global__ void finalize_kernel(const int* __restrict__ labeling) {
    int gw = blockIdx.x * 8 + (threadIdx.x >> 5);   // gw = t*32 + n
    int lane = threadIdx.x & 31;
    int t = gw >> 5, n = gw & 31;
    const float* P = g_psum + (size_t)gw * 44;
    float p = (lane < 22) ? (P[lane] + P[lane + 22]) : 0.f;
    #pragma unroll
    for (int o = 16; o > 0; o >>= 1) p += __shfl_xor_sync(0xffffffffu, p, o);
    float lse = 32.f + logf(p);
    float* dst = g_lp + ((size_t)n * 512 + t) * 64;
    const float* raw = g_lpraw + (size_t)gw * 64;
    #pragma unroll
    for (int r = 0; r < 2; r++) {
        int l = lane + r * 32;
        if (l < 61) {
            int ext = (l & 1) ? labeling[n * 30 + (l >> 1)] : 0;
            int v = g_colmap[n * 1296 + ext];
            dst[l] = raw[v - 1] - lse;
        } else if (l < 64) dst[l] = NEGINF;
    }
}

// ---------- K6: CTC log-domain, smem-staged lp, one block/sequence ----------
__global__ void __launch_bounds__(256) ctc_kernel(const int* __restrict__ labeling,
                                                  const int* __restrict__ in_lens,
                                                  const int* __restrict__ lab_lens) {
    extern __shared__ __align__(16) float2 slp[];   // [512][32] float2 = 128 KB
    const int n = blockIdx.x;
    const int tid = threadIdx.x;
    uint32_t sbase = sm2u(slp);
    const char* src = (const char*)(g_lp + (size_t)n * 512 * 64);
    #pragma unroll
    for (int it = 0; it < 32; it++) {
        int i = tid + it * 256;
        CPA16(sbase + i * 16, src + i * 16);
    }
    asm volatile("cp.async.commit_group;" ::: "memory");
    asm volatile("cp.async.wait_group 0;" ::: "memory");
    __syncthreads();
    if (tid >= 32) return;

    const int l = tid;
    int labv = (l < 30) ? labeling[n * 30 + l] : 0;
    int labp = (l >= 1 && l <= 30) ? labeling[n * 30 + l - 1] : 0;
    const bool skip = (l >= 1 && l <= 29 && labv != labp);
    const int Tlen = in_lens[n];

    float2 v0 = slp[l];
    float lo = (l == 0) ? v0.x : NEGINF;
    float hi = (l == 0) ? v0.y : NEGINF;
    float2 lp = slp[32 + l];
    for (int t = 1; t < Tlen; t++) {
        int tn = (t + 1 < 512) ? t + 1 : 511;
        float2 nxt = slp[tn * 32 + l];
        float hp = __shfl_up_sync(0xffffffffu, hi, 1);
        if (l == 0) hp = NEGINF;
        float m1 = fmaxf(lo, hp);
        float nlo = m1 + __logf(__expf(lo - m1) + __expf(hp - m1)) + lp.x;
        float a3 = skip ? hp : NEGINF;
        float m2 = fmaxf(hi, fmaxf(lo, a3));
        float nhi = m2 + __logf(__expf(hi - m2) + __expf(lo - m2) + __expf(a3 - m2)) + lp.y;
        lo = nlo; hi = nhi; lp = nxt;
    }
    int lab = lab_lens[n];
    float x = __shfl_sync(0xffffffffu, lo, lab);       // alpha[2*lab]
    float y = __shfl_sync(0xffffffffu, hi, lab - 1);   // alpha[2*lab-1]
    if (l == 0) {
        float mx = fmaxf(x, y);
        g_nll[n] = -(mx + logf(expf(x - mx) + expf(y - mx)));
    }
}

// ---------- K7: deterministic sum ----------
__global__ void sum_kernel(float* __restrict__ out) {
    float s = 0.f;
    #pragma unroll
    for (int n = 0; n < 32; n++) s += g_nll[n];
    out[0] = s;
}

// ---------- launch ----------
extern "C" void kernel_launch(void* const* d_in, const int* in_sizes, int n_in,
                              void* d_out, int out_size) {
    const float* feats = (const float*)d_in[0];
    const float* weight = (const float*)d_in[1];
    const int* labeling = (const int*)d_in[2];
    const int* logit_lgts = (const int*)d_in[3];
    const int* labeling_lgts = (const int*)d_in[4];
    float* out = (float*)d_out;

    cudaFuncSetAttribute(gemm_kernel, cudaFuncAttributeMaxDynamicSharedMemorySize, 98304);
    cudaFuncSetAttribute(ctc_kernel, cudaFuncAttributeMaxDynamicSharedMemorySize, 131072);

    colsum_kernel<<<dim3(41, 8), dim3(32, 8)>>>(weight);
    wtrans_kernel<<<dim3(41, 16), dim3(32, 8)>>>(weight);
    fprep_kernel<<<2048, 256>>>(feats, labeling);
    gemm_kernel<<<dim3(11, 128), 256, 98304>>>();
    finalize_kernel<<<2048, 256>>>(labeling);
    ctc_kernel<<<32, 256, 131072>>>(labeling, logit_lgts, labeling_lgts);
    sum_kernel<<<1, 1>>>(out);
}